// round 15
// baseline (speedup 1.0000x reference)
#include <cuda_runtime.h>
#include <math.h>

// Problem constants
#define Sn 8192
#define Dn 2048
#define En 64
#define Cn 128
#define MAXN 1024   // max tokens gathered per expert (mean 128, sigma ~11)

#define GEMM_BLOCKS 256      // 128 M-tiles x splitK 2
#define FILL_ONLY 188        // pads grid to 444 = 3 blocks/SM exactly
#define TOTAL_BLOCKS (GEMM_BLOCKS + FILL_ONLY)
#define MTILES 128

static const long long SECn = (long long)Sn * En * Cn;  // 67,108,864

// ---------------- device scratch (no allocations allowed) ----------------
// Replay invariants: g_cnt zero at every launch start (zero at load; reset by
// capacity_kernel after use). g_tick is parity-based, never reset.
__device__ float g_part[2 * Sn * En];      // split-K partial logits, 4MB
__device__ float g_gate[Sn];               // gate value at argmax expert
__device__ int   g_list[En * MAXN];        // per-expert gathered token indices
__device__ float g_colsum_p[MTILES][En];   // per-tile gate column sums
__device__ int   g_cnt[En];                // expert counts (reset each launch)
__device__ int   g_tick[MTILES];           // split-K arrival tickets (parity)

// packed f32x2 helpers (per-lane identical to fmaf -> bit-faithful logits)
__device__ __forceinline__ unsigned long long pk2(float lo, float hi) {
    unsigned long long r;
    asm("mov.b64 %0, {%1, %2};" : "=l"(r) : "f"(lo), "f"(hi));
    return r;
}
__device__ __forceinline__ void fma2(unsigned long long& d, unsigned long long a,
                                     unsigned long long b) {
    asm("fma.rn.f32x2 %0, %1, %2, %0;" : "+l"(d) : "l"(a), "l"(b));
}
__device__ __forceinline__ void upk2(float& lo, float& hi, unsigned long long v) {
    asm("mov.b64 {%0, %1}, %2;" : "=f"(lo), "=f"(hi) : "l"(v));
}

// ---------------- fused GEMM + zero-fill + softmax/list epilogue ----------------
// 444 blocks x 256 threads = exactly 3 blocks/SM: every SM keeps at least one
// barrier-free fill-only block streaming stores while GEMM blocks are in
// load/FMA phases -> store pipe never idles. GEMM math/epilogue identical to
// the R11/R14 passing kernels (bit-faithful logits & selection).
__global__ __launch_bounds__(256) void gemm_fill_kernel(const float* __restrict__ x,
                                                        const float* __restrict__ wg,
                                                        float* __restrict__ out,
                                                        long long out_size) {
    const int bid = blockIdx.x;
    const int tid = threadIdx.x;

    const long long n4 = out_size >> 2;                         // float4 count
    const long long s = (n4 + (GEMM_BLOCKS + 2 * FILL_ONLY) - 1) / (GEMM_BLOCKS + 2 * FILL_ONLY);
    const float4 z4 = make_float4(0.f, 0.f, 0.f, 0.f);

    if (bid >= GEMM_BLOCKS) {
        // ---- fill-only block: 2x slice ----
        const long long j = bid - GEMM_BLOCKS;
        long long lo = (long long)GEMM_BLOCKS * s + j * 2 * s;
        long long hiq = lo + 2 * s; if (hiq > n4) hiq = n4;
#pragma unroll 4
        for (long long i = lo + tid; i < hiq; i += 256)
            *(float4*)(out + (i << 2)) = z4;
        return;
    }

    // ---- GEMM block ----
    __shared__ float xsT[32][68];
    __shared__ float wsT[32][68];
    __shared__ float scs[En];
    __shared__ int s_last;

    const int mtile = bid & 127;
    const int m0 = mtile * 64;
    const int k0 = (bid >> 7) * 1024;
    const int tx = tid & 15;   // expert group (4 experts)
    const int ty = tid >> 4;   // token group (4 tokens = 2 pairs)

    const long long lo = (long long)bid * s;
    long long hiq = lo + s; if (hiq > n4) hiq = n4;
    const long long pc = (s + 31) >> 5;            // per-chunk fill quota

    unsigned long long acc2[2][4];       // [token pair][expert], f32x2
#pragma unroll
    for (int p = 0; p < 2; p++)
#pragma unroll
        for (int j = 0; j < 4; j++) acc2[p][j] = 0ull;

    for (int kb = 0; kb < 1024; kb += 32) {
#pragma unroll
        for (int i = 0; i < 2; i++) {
            int v = tid + i * 256;       // 0..511
            int row = v >> 3;            // 0..63
            int kq = v & 7;              // 0..7 (float4 along K)
            const float4 xv = *(const float4*)(x + (size_t)(m0 + row) * Dn + (k0 + kb + (kq << 2)));
            xsT[(kq << 2) + 0][row] = xv.x;
            xsT[(kq << 2) + 1][row] = xv.y;
            xsT[(kq << 2) + 2][row] = xv.z;
            xsT[(kq << 2) + 3][row] = xv.w;
            const float4 wv = *(const float4*)(wg + (size_t)row * Dn + (k0 + kb + (kq << 2)));
            wsT[(kq << 2) + 0][row] = wv.x;
            wsT[(kq << 2) + 1][row] = wv.y;
            wsT[(kq << 2) + 2][row] = wv.z;
            wsT[(kq << 2) + 3][row] = wv.w;
        }
        __syncthreads();

        // interleaved zero-fill: this chunk's sub-range of the block's slice
        {
            long long s0 = lo + (long long)(kb >> 5) * pc;
            long long s1 = s0 + pc; if (s1 > hiq) s1 = hiq;
            for (long long i = s0 + tid; i < s1; i += 256)
                *(float4*)(out + (i << 2)) = z4;
        }

#pragma unroll
        for (int kk = 0; kk < 32; kk++) {
            // 4 tokens arrive pre-packed as 2 f32x2 (consecutive floats)
            const ulonglong2 av = *(const ulonglong2*)&xsT[kk][ty << 2];
            const float4 b = *(const float4*)&wsT[kk][tx << 2];
            unsigned long long bv2[4] = {pk2(b.x, b.x), pk2(b.y, b.y),
                                         pk2(b.z, b.z), pk2(b.w, b.w)};
#pragma unroll
            for (int j = 0; j < 4; j++) {
                fma2(acc2[0][j], av.x, bv2[j]);
                fma2(acc2[1][j], av.y, bv2[j]);
            }
        }
        __syncthreads();
    }

    // store partial logits (same layout as all passing rounds)
    float* op = g_part + (size_t)(bid >> 7) * (Sn * En);
#pragma unroll
    for (int p = 0; p < 2; p++) {
        float l0, h0, l1, h1, l2, h2, l3, h3;
        upk2(l0, h0, acc2[p][0]);
        upk2(l1, h1, acc2[p][1]);
        upk2(l2, h2, acc2[p][2]);
        upk2(l3, h3, acc2[p][3]);
        float4 vlo = make_float4(l0, l1, l2, l3);   // token ty*4 + 2p
        float4 vhi = make_float4(h0, h1, h2, h3);   // token ty*4 + 2p + 1
        *(float4*)(op + (size_t)(m0 + (ty << 2) + 2 * p) * En + (tx << 2)) = vlo;
        *(float4*)(op + (size_t)(m0 + (ty << 2) + 2 * p + 1) * En + (tx << 2)) = vhi;
    }

    // ---- per-tile parity ticket: last split-K block runs the epilogue ----
    __threadfence();            // release our g_part stores
    __syncthreads();
    if (tid == 0) s_last = (atomicAdd(&g_tick[mtile], 1) & 1);
    __syncthreads();
    if (!s_last) return;
    __threadfence();            // acquire peer's g_part stores

    if (tid < En) scs[tid] = 0.f;
    __syncthreads();

    // softmax/argmax for this tile's 64 tokens (identical arithmetic: p0+p1)
    {
        const int warp = tid >> 5;
        const int lane = tid & 31;
        for (int q = 0; q < 8; q++) {
            const int sdx = m0 + warp * 8 + q;
            const float* p0 = g_part + (size_t)sdx * En;
            const float* p1 = g_part + (size_t)(Sn * En) + (size_t)sdx * En;
            float v0 = p0[lane] + p1[lane];
            float v1 = p0[lane + 32] + p1[lane + 32];

            float m = fmaxf(v0, v1);
#pragma unroll
            for (int o = 16; o; o >>= 1) m = fmaxf(m, __shfl_xor_sync(0xffffffffu, m, o));

            float e0 = expf(v0 - m), e1 = expf(v1 - m);
            float ss = e0 + e1;
#pragma unroll
            for (int o = 16; o; o >>= 1) ss += __shfl_xor_sync(0xffffffffu, ss, o);
            float inv = 1.0f / ss;
            float gg0 = e0 * inv, gg1 = e1 * inv;

            float bv; int bi;
            if (v0 >= v1) { bv = v0; bi = lane; } else { bv = v1; bi = lane + 32; }
#pragma unroll
            for (int o = 16; o; o >>= 1) {
                float ov = __shfl_xor_sync(0xffffffffu, bv, o);
                int oi = __shfl_xor_sync(0xffffffffu, bi, o);
                if (ov > bv || (ov == bv && oi < bi)) { bv = ov; bi = oi; }
            }
            float gsel = __shfl_sync(0xffffffffu, (bi < 32) ? gg0 : gg1, bi & 31);

            atomicAdd(&scs[lane], gg0);
            atomicAdd(&scs[lane + 32], gg1);
            if (lane == 0) {
                g_gate[sdx] = gsel;
                int p = atomicAdd(&g_cnt[bi], 1);   // zero at launch start (invariant)
                if (p < MAXN) g_list[bi * MAXN + p] = sdx;
            }
        }
    }
    __syncthreads();
    if (tid < En) g_colsum_p[mtile][tid] = scs[tid];
}

// ---------------- exact JAX threefry2x32 noise (partitionable path) ----------------
__device__ __forceinline__ unsigned rotl32(unsigned v, int d) {
    return (v << d) | (v >> (32 - d));
}
__device__ __forceinline__ float jax_noise(int s, int e) {
    unsigned x0 = 0u;
    unsigned x1 = (unsigned)(s * En + e);

    const unsigned ks0 = 0u;
    const unsigned ks1 = 42u;
    const unsigned ks2 = 0u ^ 42u ^ 0x1BD11BDAu;

    x0 += ks0; x1 += ks1;
#define TF_ROUND(R) { x0 += x1; x1 = rotl32(x1, R); x1 ^= x0; }
    TF_ROUND(13) TF_ROUND(15) TF_ROUND(26) TF_ROUND(6)
    x0 += ks1; x1 += ks2 + 1u;
    TF_ROUND(17) TF_ROUND(29) TF_ROUND(16) TF_ROUND(24)
    x0 += ks2; x1 += ks0 + 2u;
    TF_ROUND(13) TF_ROUND(15) TF_ROUND(26) TF_ROUND(6)
    x0 += ks0; x1 += ks1 + 3u;
    TF_ROUND(17) TF_ROUND(29) TF_ROUND(16) TF_ROUND(24)
    x0 += ks1; x1 += ks2 + 4u;
    TF_ROUND(13) TF_ROUND(15) TF_ROUND(26) TF_ROUND(6)
    x0 += ks2; x1 += ks0 + 5u;
#undef TF_ROUND
    unsigned bits = x0 ^ x1;
    return __uint_as_float((bits >> 9) | 0x3F800000u) - 1.0f;
}

// ---------------- capacity selection + scatter + l_aux + exp_counts ----------------
// (byte-identical to R14: per-thread element ownership, gate prefetch,
//  unrolled dual-accumulator scans)
__global__ __launch_bounds__(256) void capacity_kernel(float* __restrict__ out,
                                                       long long out_size) {
    const int e = blockIdx.x;
    __shared__ int   sidx[MAXN];
    __shared__ float snoi[MAXN];
    __shared__ float sgat[MAXN];
    __shared__ char  skeep[MAXN];
    __shared__ float cred[MTILES];

    const int nraw = g_cnt[e];
    const int n = nraw < MAXN ? nraw : MAXN;

    // load list + gate (overlapping LDGs), compute noise while loads fly
    for (int i = threadIdx.x; i < n; i += 256) {
        int sdx = g_list[e * MAXN + i];
        float gv = g_gate[sdx];
        sidx[i] = sdx;
        snoi[i] = jax_noise(sdx, e);
        sgat[i] = gv;
    }
    // start the l_aux partial load early (independent of the lists)
    if (threadIdx.x < MTILES) cred[threadIdx.x] = g_colsum_p[threadIdx.x][e];
    __syncthreads();

    // keep = rank < capacity by (noise desc, index asc); lax.top_k is index-stable
    for (int i = threadIdx.x; i < n; i += 256) {
        char k = 1;
        if (n > Cn) {
            const float ni = snoi[i];
            const int ii = sidx[i];
            int r0 = 0, r1 = 0;
            int jj = 0;
#pragma unroll 4
            for (; jj + 1 < n; jj += 2) {
                float na = snoi[jj],   nb = snoi[jj + 1];
                int   ia = sidx[jj],   ib = sidx[jj + 1];
                r0 += (na > ni) || (na == ni && ia < ii);
                r1 += (nb > ni) || (nb == ni && ib < ii);
            }
            if (jj < n) {
                float na = snoi[jj];
                r0 += (na > ni) || (na == ni && sidx[jj] < ii);
            }
            k = ((r0 + r1) < Cn) ? 1 : 0;
        }
        skeep[i] = k;
    }
    __syncthreads();

    // slot = rank by token index among kept (cumsum semantics); scatter outputs
    for (int i = threadIdx.x; i < n; i += 256) {
        if (!skeep[i]) continue;
        const int ii = sidx[i];
        int s0 = 0, s1 = 0;
        int jj = 0;
#pragma unroll 4
        for (; jj + 1 < n; jj += 2) {
            s0 += (skeep[jj] && sidx[jj] < ii);
            s1 += (skeep[jj + 1] && sidx[jj + 1] < ii);
        }
        if (jj < n) s0 += (skeep[jj] && sidx[jj] < ii);
        int slot = s0 + s1;
        long long r = (long long)ii * En + e;
        long long p = 1 + r * (long long)Cn + slot;
        if (p < out_size) out[p] = sgat[i];
        if (p + SECn < out_size) out[p + SECn] = 1.0f;
    }

    // exp_counts[e] + reset count (restore zero invariant for next launch)
    if (threadIdx.x == 0) {
        long long idx = 1 + 2 * SECn + e;
        if (idx < out_size) out[idx] = (float)nraw;
        g_cnt[e] = 0;
    }

    // l_aux contribution: parallel reduce of colsum_e over 128 tile partials
    __syncthreads();
    if (threadIdx.x < 64) cred[threadIdx.x] += cred[threadIdx.x + 64];
    __syncthreads();
    if (threadIdx.x < 32) {
        float v = cred[threadIdx.x] + cred[threadIdx.x + 32];
#pragma unroll
        for (int o = 16; o; o >>= 1) v += __shfl_xor_sync(0xffffffffu, v, o);
        if (threadIdx.x == 0) {
            float contrib = v * (float)nraw * ((float)En / ((float)Sn * (float)Sn));
            if (out_size > 0) atomicAdd(out, contrib);
        }
    }
}

// ---------------- launch ----------------
extern "C" void kernel_launch(void* const* d_in, const int* in_sizes, int n_in,
                              void* d_out, int out_size) {
    const float* x  = (const float*)d_in[0];   // [S, D] f32
    const float* wg = (const float*)d_in[1];   // [E, D] f32
    float* out = (float*)d_out;
    long long osz = (long long)out_size;

    gemm_fill_kernel<<<TOTAL_BLOCKS, 256>>>(x, wg, out, osz);
    capacity_kernel<<<En, 256>>>(out, osz);
}

// round 16
// speedup vs baseline: 1.0442x; 1.0442x over previous
#include <cuda_runtime.h>
#include <math.h>

// Problem constants
#define Sn 8192
#define Dn 2048
#define En 64
#define Cn 128
#define MAXN 1024   // max tokens gathered per expert (mean 128, sigma ~11)

#define GEMM_BLOCKS 256      // 128 M-tiles x splitK 2
#define FILL_ONLY 40         // pads grid to 296 = 2 blocks/SM exactly
#define TOTAL_BLOCKS (GEMM_BLOCKS + FILL_ONLY)
#define MTILES 128

static const long long SECn = (long long)Sn * En * Cn;  // 67,108,864

// ---------------- device scratch (no allocations allowed) ----------------
// Replay invariants: g_cnt zero at every launch start (zero at load; reset by
// capacity_kernel after use). g_tick is parity-based, never reset.
__device__ float g_part[2 * Sn * En];      // split-K partial logits, 4MB
__device__ float g_gate[Sn];               // gate value at argmax expert
__device__ int   g_list[En * MAXN];        // per-expert gathered token indices
__device__ float g_colsum_p[MTILES][En];   // per-tile gate column sums
__device__ int   g_cnt[En];                // expert counts (reset each launch)
__device__ int   g_tick[MTILES];           // split-K arrival tickets (parity)

// packed f32x2 helpers (per-lane identical to fmaf -> bit-faithful logits)
__device__ __forceinline__ unsigned long long pk2(float lo, float hi) {
    unsigned long long r;
    asm("mov.b64 %0, {%1, %2};" : "=l"(r) : "f"(lo), "f"(hi));
    return r;
}
__device__ __forceinline__ void fma2(unsigned long long& d, unsigned long long a,
                                     unsigned long long b) {
    asm("fma.rn.f32x2 %0, %1, %2, %0;" : "+l"(d) : "l"(a), "l"(b));
}
__device__ __forceinline__ void upk2(float& lo, float& hi, unsigned long long v) {
    asm("mov.b64 {%0, %1}, %2;" : "=f"(lo), "=f"(hi) : "l"(v));
}

// ---------------- fused GEMM + zero-fill + softmax/list epilogue ----------------
// R14 structure (296 blocks, 2/SM) with DOUBLE-BUFFERED smem tiles: iteration
// it loads tile it+1 into buf[it+1 & 1] (LDG->STS, scoreboarded) while FMA
// reads buf[it & 1]; one barrier per iteration both publishes the next buffer
// and retires reads of the current one -> DRAM read latency fully hidden
// under fill-stores + FMA. FMA order unchanged -> bit-identical logits.
__global__ __launch_bounds__(256) void gemm_fill_kernel(const float* __restrict__ x,
                                                        const float* __restrict__ wg,
                                                        float* __restrict__ out,
                                                        long long out_size) {
    const int bid = blockIdx.x;
    const int tid = threadIdx.x;

    const long long n4 = out_size >> 2;                         // float4 count
    const long long s = (n4 + (GEMM_BLOCKS + 2 * FILL_ONLY) - 1) / (GEMM_BLOCKS + 2 * FILL_ONLY);
    const float4 z4 = make_float4(0.f, 0.f, 0.f, 0.f);

    if (bid >= GEMM_BLOCKS) {
        // ---- fill-only block: 2x slice ----
        const long long j = bid - GEMM_BLOCKS;
        long long lo = (long long)GEMM_BLOCKS * s + j * 2 * s;
        long long hiq = lo + 2 * s; if (hiq > n4) hiq = n4;
#pragma unroll 4
        for (long long i = lo + tid; i < hiq; i += 256)
            *(float4*)(out + (i << 2)) = z4;
        return;
    }

    // ---- GEMM block ----
    __shared__ float xsT[2][32][68];
    __shared__ float wsT[2][32][68];
    __shared__ float scs[En];
    __shared__ int s_last;

    const int mtile = bid & 127;
    const int m0 = mtile * 64;
    const int k0 = (bid >> 7) * 1024;
    const int tx = tid & 15;   // expert group (4 experts)
    const int ty = tid >> 4;   // token group (4 tokens = 2 pairs)

    const long long lo = (long long)bid * s;
    long long hiq = lo + s; if (hiq > n4) hiq = n4;
    const long long pc = (s + 31) >> 5;            // per-chunk fill quota

    // tile loader: global (k0+kb) -> smem buffer b (transposed)
    auto loadtile = [&](int kb, int b) {
#pragma unroll
        for (int i = 0; i < 2; i++) {
            int v = tid + i * 256;       // 0..511
            int row = v >> 3;            // 0..63
            int kq = v & 7;              // 0..7 (float4 along K)
            const float4 xv = *(const float4*)(x + (size_t)(m0 + row) * Dn + (k0 + kb + (kq << 2)));
            xsT[b][(kq << 2) + 0][row] = xv.x;
            xsT[b][(kq << 2) + 1][row] = xv.y;
            xsT[b][(kq << 2) + 2][row] = xv.z;
            xsT[b][(kq << 2) + 3][row] = xv.w;
            const float4 wv = *(const float4*)(wg + (size_t)row * Dn + (k0 + kb + (kq << 2)));
            wsT[b][(kq << 2) + 0][row] = wv.x;
            wsT[b][(kq << 2) + 1][row] = wv.y;
            wsT[b][(kq << 2) + 2][row] = wv.z;
            wsT[b][(kq << 2) + 3][row] = wv.w;
        }
    };

    unsigned long long acc2[2][4];       // [token pair][expert], f32x2
#pragma unroll
    for (int p = 0; p < 2; p++)
#pragma unroll
        for (int j = 0; j < 4; j++) acc2[p][j] = 0ull;

    loadtile(0, 0);                      // preload tile 0
    __syncthreads();

    for (int it = 0; it < 32; it++) {
        const int cur = it & 1;
        if (it + 1 < 32) loadtile((it + 1) << 5, cur ^ 1);   // prefetch next tile

        // interleaved zero-fill: this chunk's sub-range of the block's slice
        {
            long long s0 = lo + (long long)it * pc;
            long long s1 = s0 + pc; if (s1 > hiq) s1 = hiq;
            for (long long i = s0 + tid; i < s1; i += 256)
                *(float4*)(out + (i << 2)) = z4;
        }

#pragma unroll
        for (int kk = 0; kk < 32; kk++) {
            // 4 tokens arrive pre-packed as 2 f32x2 (consecutive floats)
            const ulonglong2 av = *(const ulonglong2*)&xsT[cur][kk][ty << 2];
            const float4 b = *(const float4*)&wsT[cur][kk][tx << 2];
            unsigned long long bv2[4] = {pk2(b.x, b.x), pk2(b.y, b.y),
                                         pk2(b.z, b.z), pk2(b.w, b.w)};
#pragma unroll
            for (int j = 0; j < 4; j++) {
                fma2(acc2[0][j], av.x, bv2[j]);
                fma2(acc2[1][j], av.y, bv2[j]);
            }
        }
        __syncthreads();   // publish buf cur^1, retire reads of buf cur
    }

    // store partial logits (same layout as all passing rounds)
    float* op = g_part + (size_t)(bid >> 7) * (Sn * En);
#pragma unroll
    for (int p = 0; p < 2; p++) {
        float l0, h0, l1, h1, l2, h2, l3, h3;
        upk2(l0, h0, acc2[p][0]);
        upk2(l1, h1, acc2[p][1]);
        upk2(l2, h2, acc2[p][2]);
        upk2(l3, h3, acc2[p][3]);
        float4 vlo = make_float4(l0, l1, l2, l3);   // token ty*4 + 2p
        float4 vhi = make_float4(h0, h1, h2, h3);   // token ty*4 + 2p + 1
        *(float4*)(op + (size_t)(m0 + (ty << 2) + 2 * p) * En + (tx << 2)) = vlo;
        *(float4*)(op + (size_t)(m0 + (ty << 2) + 2 * p + 1) * En + (tx << 2)) = vhi;
    }

    // ---- per-tile parity ticket: last split-K block runs the epilogue ----
    __threadfence();            // release our g_part stores
    __syncthreads();
    if (tid == 0) s_last = (atomicAdd(&g_tick[mtile], 1) & 1);
    __syncthreads();
    if (!s_last) return;
    __threadfence();            // acquire peer's g_part stores

    if (tid < En) scs[tid] = 0.f;
    __syncthreads();

    // softmax/argmax for this tile's 64 tokens (identical arithmetic: p0+p1)
    {
        const int warp = tid >> 5;
        const int lane = tid & 31;
        for (int q = 0; q < 8; q++) {
            const int sdx = m0 + warp * 8 + q;
            const float* p0 = g_part + (size_t)sdx * En;
            const float* p1 = g_part + (size_t)(Sn * En) + (size_t)sdx * En;
            float v0 = p0[lane] + p1[lane];
            float v1 = p0[lane + 32] + p1[lane + 32];

            float m = fmaxf(v0, v1);
#pragma unroll
            for (int o = 16; o; o >>= 1) m = fmaxf(m, __shfl_xor_sync(0xffffffffu, m, o));

            float e0 = expf(v0 - m), e1 = expf(v1 - m);
            float ss = e0 + e1;
#pragma unroll
            for (int o = 16; o; o >>= 1) ss += __shfl_xor_sync(0xffffffffu, ss, o);
            float inv = 1.0f / ss;
            float gg0 = e0 * inv, gg1 = e1 * inv;

            float bv; int bi;
            if (v0 >= v1) { bv = v0; bi = lane; } else { bv = v1; bi = lane + 32; }
#pragma unroll
            for (int o = 16; o; o >>= 1) {
                float ov = __shfl_xor_sync(0xffffffffu, bv, o);
                int oi = __shfl_xor_sync(0xffffffffu, bi, o);
                if (ov > bv || (ov == bv && oi < bi)) { bv = ov; bi = oi; }
            }
            float gsel = __shfl_sync(0xffffffffu, (bi < 32) ? gg0 : gg1, bi & 31);

            atomicAdd(&scs[lane], gg0);
            atomicAdd(&scs[lane + 32], gg1);
            if (lane == 0) {
                g_gate[sdx] = gsel;
                int p = atomicAdd(&g_cnt[bi], 1);   // zero at launch start (invariant)
                if (p < MAXN) g_list[bi * MAXN + p] = sdx;
            }
        }
    }
    __syncthreads();
    if (tid < En) g_colsum_p[mtile][tid] = scs[tid];
}

// ---------------- exact JAX threefry2x32 noise (partitionable path) ----------------
__device__ __forceinline__ unsigned rotl32(unsigned v, int d) {
    return (v << d) | (v >> (32 - d));
}
__device__ __forceinline__ float jax_noise(int s, int e) {
    unsigned x0 = 0u;
    unsigned x1 = (unsigned)(s * En + e);

    const unsigned ks0 = 0u;
    const unsigned ks1 = 42u;
    const unsigned ks2 = 0u ^ 42u ^ 0x1BD11BDAu;

    x0 += ks0; x1 += ks1;
#define TF_ROUND(R) { x0 += x1; x1 = rotl32(x1, R); x1 ^= x0; }
    TF_ROUND(13) TF_ROUND(15) TF_ROUND(26) TF_ROUND(6)
    x0 += ks1; x1 += ks2 + 1u;
    TF_ROUND(17) TF_ROUND(29) TF_ROUND(16) TF_ROUND(24)
    x0 += ks2; x1 += ks0 + 2u;
    TF_ROUND(13) TF_ROUND(15) TF_ROUND(26) TF_ROUND(6)
    x0 += ks0; x1 += ks1 + 3u;
    TF_ROUND(17) TF_ROUND(29) TF_ROUND(16) TF_ROUND(24)
    x0 += ks1; x1 += ks2 + 4u;
    TF_ROUND(13) TF_ROUND(15) TF_ROUND(26) TF_ROUND(6)
    x0 += ks2; x1 += ks0 + 5u;
#undef TF_ROUND
    unsigned bits = x0 ^ x1;
    return __uint_as_float((bits >> 9) | 0x3F800000u) - 1.0f;
}

// ---------------- capacity selection + scatter + l_aux + exp_counts ----------------
// (byte-identical to R14: per-thread element ownership, gate prefetch,
//  unrolled dual-accumulator scans)
__global__ __launch_bounds__(256) void capacity_kernel(float* __restrict__ out,
                                                       long long out_size) {
    const int e = blockIdx.x;
    __shared__ int   sidx[MAXN];
    __shared__ float snoi[MAXN];
    __shared__ float sgat[MAXN];
    __shared__ char  skeep[MAXN];
    __shared__ float cred[MTILES];

    const int nraw = g_cnt[e];
    const int n = nraw < MAXN ? nraw : MAXN;

    // load list + gate (overlapping LDGs), compute noise while loads fly
    for (int i = threadIdx.x; i < n; i += 256) {
        int sdx = g_list[e * MAXN + i];
        float gv = g_gate[sdx];
        sidx[i] = sdx;
        snoi[i] = jax_noise(sdx, e);
        sgat[i] = gv;
    }
    // start the l_aux partial load early (independent of the lists)
    if (threadIdx.x < MTILES) cred[threadIdx.x] = g_colsum_p[threadIdx.x][e];
    __syncthreads();

    // keep = rank < capacity by (noise desc, index asc); lax.top_k is index-stable
    for (int i = threadIdx.x; i < n; i += 256) {
        char k = 1;
        if (n > Cn) {
            const float ni = snoi[i];
            const int ii = sidx[i];
            int r0 = 0, r1 = 0;
            int jj = 0;
#pragma unroll 4
            for (; jj + 1 < n; jj += 2) {
                float na = snoi[jj],   nb = snoi[jj + 1];
                int   ia = sidx[jj],   ib = sidx[jj + 1];
                r0 += (na > ni) || (na == ni && ia < ii);
                r1 += (nb > ni) || (nb == ni && ib < ii);
            }
            if (jj < n) {
                float na = snoi[jj];
                r0 += (na > ni) || (na == ni && sidx[jj] < ii);
            }
            k = ((r0 + r1) < Cn) ? 1 : 0;
        }
        skeep[i] = k;
    }
    __syncthreads();

    // slot = rank by token index among kept (cumsum semantics); scatter outputs
    for (int i = threadIdx.x; i < n; i += 256) {
        if (!skeep[i]) continue;
        const int ii = sidx[i];
        int s0 = 0, s1 = 0;
        int jj = 0;
#pragma unroll 4
        for (; jj + 1 < n; jj += 2) {
            s0 += (skeep[jj] && sidx[jj] < ii);
            s1 += (skeep[jj + 1] && sidx[jj + 1] < ii);
        }
        if (jj < n) s0 += (skeep[jj] && sidx[jj] < ii);
        int slot = s0 + s1;
        long long r = (long long)ii * En + e;
        long long p = 1 + r * (long long)Cn + slot;
        if (p < out_size) out[p] = sgat[i];
        if (p + SECn < out_size) out[p + SECn] = 1.0f;
    }

    // exp_counts[e] + reset count (restore zero invariant for next launch)
    if (threadIdx.x == 0) {
        long long idx = 1 + 2 * SECn + e;
        if (idx < out_size) out[idx] = (float)nraw;
        g_cnt[e] = 0;
    }

    // l_aux contribution: parallel reduce of colsum_e over 128 tile partials
    __syncthreads();
    if (threadIdx.x < 64) cred[threadIdx.x] += cred[threadIdx.x + 64];
    __syncthreads();
    if (threadIdx.x < 32) {
        float v = cred[threadIdx.x] + cred[threadIdx.x + 32];
#pragma unroll
        for (int o = 16; o; o >>= 1) v += __shfl_xor_sync(0xffffffffu, v, o);
        if (threadIdx.x == 0) {
            float contrib = v * (float)nraw * ((float)En / ((float)Sn * (float)Sn));
            if (out_size > 0) atomicAdd(out, contrib);
        }
    }
}

// ---------------- launch ----------------
extern "C" void kernel_launch(void* const* d_in, const int* in_sizes, int n_in,
                              void* d_out, int out_size) {
    const float* x  = (const float*)d_in[0];   // [S, D] f32
    const float* wg = (const float*)d_in[1];   // [E, D] f32
    float* out = (float*)d_out;
    long long osz = (long long)out_size;

    gemm_fill_kernel<<<TOTAL_BLOCKS, 256>>>(x, wg, out, osz);
    capacity_kernel<<<En, 256>>>(out, osz);
}

// round 17
// speedup vs baseline: 1.0711x; 1.0257x over previous
#include <cuda_runtime.h>
#include <math.h>

// Problem constants
#define Sn 8192
#define Dn 2048
#define En 64
#define Cn 128
#define MAXN 1024   // max tokens gathered per expert (mean 128, sigma ~11)

#define GEMM_BLOCKS 256      // 128 M-tiles x splitK 2
#define FILL_ONLY 40         // pads grid to 296 = 2 blocks/SM exactly
#define TOTAL_BLOCKS (GEMM_BLOCKS + FILL_ONLY)
#define MTILES 128

static const long long SECn = (long long)Sn * En * Cn;  // 67,108,864

// ---------------- device scratch (no allocations allowed) ----------------
// Replay invariants: g_cnt zero at every launch start (zero at load; reset by
// capacity_kernel after use). g_tick is parity-based, never reset.
__device__ float g_part[2 * Sn * En];      // split-K partial logits, 4MB
__device__ float g_gate[Sn];               // gate value at argmax expert
__device__ int   g_list[En * MAXN];        // per-expert gathered token indices
__device__ float g_colsum_p[MTILES][En];   // per-tile gate column sums
__device__ int   g_cnt[En];                // expert counts (reset each launch)
__device__ int   g_tick[MTILES];           // split-K arrival tickets (parity)

// packed f32x2 helpers (per-lane identical to fmaf -> bit-faithful logits)
__device__ __forceinline__ unsigned long long pk2(float lo, float hi) {
    unsigned long long r;
    asm("mov.b64 %0, {%1, %2};" : "=l"(r) : "f"(lo), "f"(hi));
    return r;
}
__device__ __forceinline__ void fma2(unsigned long long& d, unsigned long long a,
                                     unsigned long long b) {
    asm("fma.rn.f32x2 %0, %1, %2, %0;" : "+l"(d) : "l"(a), "l"(b));
}
__device__ __forceinline__ void upk2(float& lo, float& hi, unsigned long long v) {
    asm("mov.b64 {%0, %1}, %2;" : "=f"(lo), "=f"(hi) : "l"(v));
}

// ---------------- fused GEMM + zero-fill + softmax/list epilogue ----------------
// (byte-identical compute to R16 best; adds only the PDL trigger)
__global__ __launch_bounds__(256) void gemm_fill_kernel(const float* __restrict__ x,
                                                        const float* __restrict__ wg,
                                                        float* __restrict__ out,
                                                        long long out_size) {
    const int bid = blockIdx.x;
    const int tid = threadIdx.x;

    const long long n4 = out_size >> 2;                         // float4 count
    const long long s = (n4 + (GEMM_BLOCKS + 2 * FILL_ONLY) - 1) / (GEMM_BLOCKS + 2 * FILL_ONLY);
    const float4 z4 = make_float4(0.f, 0.f, 0.f, 0.f);

    if (bid >= GEMM_BLOCKS) {
        // ---- fill-only block: 2x slice ----
        const long long j = bid - GEMM_BLOCKS;
        long long lo = (long long)GEMM_BLOCKS * s + j * 2 * s;
        long long hiq = lo + 2 * s; if (hiq > n4) hiq = n4;
#pragma unroll 4
        for (long long i = lo + tid; i < hiq; i += 256)
            *(float4*)(out + (i << 2)) = z4;
        cudaTriggerProgrammaticLaunchCompletion();
        return;
    }

    // ---- GEMM block ----
    __shared__ float xsT[2][32][68];
    __shared__ float wsT[2][32][68];
    __shared__ float scs[En];
    __shared__ int s_last;

    const int mtile = bid & 127;
    const int m0 = mtile * 64;
    const int k0 = (bid >> 7) * 1024;
    const int tx = tid & 15;   // expert group (4 experts)
    const int ty = tid >> 4;   // token group (4 tokens = 2 pairs)

    const long long lo = (long long)bid * s;
    long long hiq = lo + s; if (hiq > n4) hiq = n4;
    const long long pc = (s + 31) >> 5;            // per-chunk fill quota

    // tile loader: global (k0+kb) -> smem buffer b (transposed)
    auto loadtile = [&](int kb, int b) {
#pragma unroll
        for (int i = 0; i < 2; i++) {
            int v = tid + i * 256;       // 0..511
            int row = v >> 3;            // 0..63
            int kq = v & 7;              // 0..7 (float4 along K)
            const float4 xv = *(const float4*)(x + (size_t)(m0 + row) * Dn + (k0 + kb + (kq << 2)));
            xsT[b][(kq << 2) + 0][row] = xv.x;
            xsT[b][(kq << 2) + 1][row] = xv.y;
            xsT[b][(kq << 2) + 2][row] = xv.z;
            xsT[b][(kq << 2) + 3][row] = xv.w;
            const float4 wv = *(const float4*)(wg + (size_t)row * Dn + (k0 + kb + (kq << 2)));
            wsT[b][(kq << 2) + 0][row] = wv.x;
            wsT[b][(kq << 2) + 1][row] = wv.y;
            wsT[b][(kq << 2) + 2][row] = wv.z;
            wsT[b][(kq << 2) + 3][row] = wv.w;
        }
    };

    unsigned long long acc2[2][4];       // [token pair][expert], f32x2
#pragma unroll
    for (int p = 0; p < 2; p++)
#pragma unroll
        for (int j = 0; j < 4; j++) acc2[p][j] = 0ull;

    loadtile(0, 0);                      // preload tile 0
    __syncthreads();

    for (int it = 0; it < 32; it++) {
        const int cur = it & 1;
        if (it + 1 < 32) loadtile((it + 1) << 5, cur ^ 1);   // prefetch next tile

        // interleaved zero-fill: this chunk's sub-range of the block's slice
        {
            long long s0 = lo + (long long)it * pc;
            long long s1 = s0 + pc; if (s1 > hiq) s1 = hiq;
            for (long long i = s0 + tid; i < s1; i += 256)
                *(float4*)(out + (i << 2)) = z4;
        }

#pragma unroll
        for (int kk = 0; kk < 32; kk++) {
            // 4 tokens arrive pre-packed as 2 f32x2 (consecutive floats)
            const ulonglong2 av = *(const ulonglong2*)&xsT[cur][kk][ty << 2];
            const float4 b = *(const float4*)&wsT[cur][kk][tx << 2];
            unsigned long long bv2[4] = {pk2(b.x, b.x), pk2(b.y, b.y),
                                         pk2(b.z, b.z), pk2(b.w, b.w)};
#pragma unroll
            for (int j = 0; j < 4; j++) {
                fma2(acc2[0][j], av.x, bv2[j]);
                fma2(acc2[1][j], av.y, bv2[j]);
            }
        }
        __syncthreads();   // publish buf cur^1, retire reads of buf cur
    }

    // store partial logits (same layout as all passing rounds)
    float* op = g_part + (size_t)(bid >> 7) * (Sn * En);
#pragma unroll
    for (int p = 0; p < 2; p++) {
        float l0, h0, l1, h1, l2, h2, l3, h3;
        upk2(l0, h0, acc2[p][0]);
        upk2(l1, h1, acc2[p][1]);
        upk2(l2, h2, acc2[p][2]);
        upk2(l3, h3, acc2[p][3]);
        float4 vlo = make_float4(l0, l1, l2, l3);   // token ty*4 + 2p
        float4 vhi = make_float4(h0, h1, h2, h3);   // token ty*4 + 2p + 1
        *(float4*)(op + (size_t)(m0 + (ty << 2) + 2 * p) * En + (tx << 2)) = vlo;
        *(float4*)(op + (size_t)(m0 + (ty << 2) + 2 * p + 1) * En + (tx << 2)) = vhi;
    }

    // PDL: main work done; let the dependent capacity launch ramp up while
    // the (short) epilogue runs. It still waits for FULL grid completion via
    // cudaGridDependencySynchronize before touching our outputs.
    cudaTriggerProgrammaticLaunchCompletion();

    // ---- per-tile parity ticket: last split-K block runs the epilogue ----
    __threadfence();            // release our g_part stores
    __syncthreads();
    if (tid == 0) s_last = (atomicAdd(&g_tick[mtile], 1) & 1);
    __syncthreads();
    if (!s_last) return;
    __threadfence();            // acquire peer's g_part stores

    if (tid < En) scs[tid] = 0.f;
    __syncthreads();

    // softmax/argmax for this tile's 64 tokens (identical arithmetic: p0+p1)
    {
        const int warp = tid >> 5;
        const int lane = tid & 31;
        for (int q = 0; q < 8; q++) {
            const int sdx = m0 + warp * 8 + q;
            const float* p0 = g_part + (size_t)sdx * En;
            const float* p1 = g_part + (size_t)(Sn * En) + (size_t)sdx * En;
            float v0 = p0[lane] + p1[lane];
            float v1 = p0[lane + 32] + p1[lane + 32];

            float m = fmaxf(v0, v1);
#pragma unroll
            for (int o = 16; o; o >>= 1) m = fmaxf(m, __shfl_xor_sync(0xffffffffu, m, o));

            float e0 = expf(v0 - m), e1 = expf(v1 - m);
            float ss = e0 + e1;
#pragma unroll
            for (int o = 16; o; o >>= 1) ss += __shfl_xor_sync(0xffffffffu, ss, o);
            float inv = 1.0f / ss;
            float gg0 = e0 * inv, gg1 = e1 * inv;

            float bv; int bi;
            if (v0 >= v1) { bv = v0; bi = lane; } else { bv = v1; bi = lane + 32; }
#pragma unroll
            for (int o = 16; o; o >>= 1) {
                float ov = __shfl_xor_sync(0xffffffffu, bv, o);
                int oi = __shfl_xor_sync(0xffffffffu, bi, o);
                if (ov > bv || (ov == bv && oi < bi)) { bv = ov; bi = oi; }
            }
            float gsel = __shfl_sync(0xffffffffu, (bi < 32) ? gg0 : gg1, bi & 31);

            atomicAdd(&scs[lane], gg0);
            atomicAdd(&scs[lane + 32], gg1);
            if (lane == 0) {
                g_gate[sdx] = gsel;
                int p = atomicAdd(&g_cnt[bi], 1);   // zero at launch start (invariant)
                if (p < MAXN) g_list[bi * MAXN + p] = sdx;
            }
        }
    }
    __syncthreads();
    if (tid < En) g_colsum_p[mtile][tid] = scs[tid];
}

// ---------------- exact JAX threefry2x32 noise (partitionable path) ----------------
__device__ __forceinline__ unsigned rotl32(unsigned v, int d) {
    return (v << d) | (v >> (32 - d));
}
__device__ __forceinline__ float jax_noise(int s, int e) {
    unsigned x0 = 0u;
    unsigned x1 = (unsigned)(s * En + e);

    const unsigned ks0 = 0u;
    const unsigned ks1 = 42u;
    const unsigned ks2 = 0u ^ 42u ^ 0x1BD11BDAu;

    x0 += ks0; x1 += ks1;
#define TF_ROUND(R) { x0 += x1; x1 = rotl32(x1, R); x1 ^= x0; }
    TF_ROUND(13) TF_ROUND(15) TF_ROUND(26) TF_ROUND(6)
    x0 += ks1; x1 += ks2 + 1u;
    TF_ROUND(17) TF_ROUND(29) TF_ROUND(16) TF_ROUND(24)
    x0 += ks2; x1 += ks0 + 2u;
    TF_ROUND(13) TF_ROUND(15) TF_ROUND(26) TF_ROUND(6)
    x0 += ks0; x1 += ks1 + 3u;
    TF_ROUND(17) TF_ROUND(29) TF_ROUND(16) TF_ROUND(24)
    x0 += ks1; x1 += ks2 + 4u;
    TF_ROUND(13) TF_ROUND(15) TF_ROUND(26) TF_ROUND(6)
    x0 += ks2; x1 += ks0 + 5u;
#undef TF_ROUND
    unsigned bits = x0 ^ x1;
    return __uint_as_float((bits >> 9) | 0x3F800000u) - 1.0f;
}

// ---------------- capacity selection + scatter + l_aux + exp_counts ----------------
// (byte-identical compute to R14/R16; adds only the PDL grid-dependency wait)
__global__ __launch_bounds__(256) void capacity_kernel(float* __restrict__ out,
                                                       long long out_size) {
    // PDL: block may be scheduled before the primary grid finishes; wait for
    // full upstream completion before consuming its outputs.
    cudaGridDependencySynchronize();

    const int e = blockIdx.x;
    __shared__ int   sidx[MAXN];
    __shared__ float snoi[MAXN];
    __shared__ float sgat[MAXN];
    __shared__ char  skeep[MAXN];
    __shared__ float cred[MTILES];

    const int nraw = g_cnt[e];
    const int n = nraw < MAXN ? nraw : MAXN;

    // load list + gate (overlapping LDGs), compute noise while loads fly
    for (int i = threadIdx.x; i < n; i += 256) {
        int sdx = g_list[e * MAXN + i];
        float gv = g_gate[sdx];
        sidx[i] = sdx;
        snoi[i] = jax_noise(sdx, e);
        sgat[i] = gv;
    }
    // start the l_aux partial load early (independent of the lists)
    if (threadIdx.x < MTILES) cred[threadIdx.x] = g_colsum_p[threadIdx.x][e];
    __syncthreads();

    // keep = rank < capacity by (noise desc, index asc); lax.top_k is index-stable
    for (int i = threadIdx.x; i < n; i += 256) {
        char k = 1;
        if (n > Cn) {
            const float ni = snoi[i];
            const int ii = sidx[i];
            int r0 = 0, r1 = 0;
            int jj = 0;
#pragma unroll 4
            for (; jj + 1 < n; jj += 2) {
                float na = snoi[jj],   nb = snoi[jj + 1];
                int   ia = sidx[jj],   ib = sidx[jj + 1];
                r0 += (na > ni) || (na == ni && ia < ii);
                r1 += (nb > ni) || (nb == ni && ib < ii);
            }
            if (jj < n) {
                float na = snoi[jj];
                r0 += (na > ni) || (na == ni && sidx[jj] < ii);
            }
            k = ((r0 + r1) < Cn) ? 1 : 0;
        }
        skeep[i] = k;
    }
    __syncthreads();

    // slot = rank by token index among kept (cumsum semantics); scatter outputs
    for (int i = threadIdx.x; i < n; i += 256) {
        if (!skeep[i]) continue;
        const int ii = sidx[i];
        int s0 = 0, s1 = 0;
        int jj = 0;
#pragma unroll 4
        for (; jj + 1 < n; jj += 2) {
            s0 += (skeep[jj] && sidx[jj] < ii);
            s1 += (skeep[jj + 1] && sidx[jj + 1] < ii);
        }
        if (jj < n) s0 += (skeep[jj] && sidx[jj] < ii);
        int slot = s0 + s1;
        long long r = (long long)ii * En + e;
        long long p = 1 + r * (long long)Cn + slot;
        if (p < out_size) out[p] = sgat[i];
        if (p + SECn < out_size) out[p + SECn] = 1.0f;
    }

    // exp_counts[e] + reset count (restore zero invariant for next launch)
    if (threadIdx.x == 0) {
        long long idx = 1 + 2 * SECn + e;
        if (idx < out_size) out[idx] = (float)nraw;
        g_cnt[e] = 0;
    }

    // l_aux contribution: parallel reduce of colsum_e over 128 tile partials
    __syncthreads();
    if (threadIdx.x < 64) cred[threadIdx.x] += cred[threadIdx.x + 64];
    __syncthreads();
    if (threadIdx.x < 32) {
        float v = cred[threadIdx.x] + cred[threadIdx.x + 32];
#pragma unroll
        for (int o = 16; o; o >>= 1) v += __shfl_xor_sync(0xffffffffu, v, o);
        if (threadIdx.x == 0) {
            float contrib = v * (float)nraw * ((float)En / ((float)Sn * (float)Sn));
            if (out_size > 0) atomicAdd(out, contrib);
        }
    }
}

// ---------------- launch ----------------
extern "C" void kernel_launch(void* const* d_in, const int* in_sizes, int n_in,
                              void* d_out, int out_size) {
    const float* x  = (const float*)d_in[0];   // [S, D] f32
    const float* wg = (const float*)d_in[1];   // [E, D] f32
    float* out = (float*)d_out;
    long long osz = (long long)out_size;

    gemm_fill_kernel<<<TOTAL_BLOCKS, 256>>>(x, wg, out, osz);

    // PDL launch for capacity: overlap its ramp with the primary's tail.
    cudaLaunchConfig_t cfg = {};
    cfg.gridDim = dim3(En, 1, 1);
    cfg.blockDim = dim3(256, 1, 1);
    cudaLaunchAttribute attrs[1];
    attrs[0].id = cudaLaunchAttributeProgrammaticStreamSerialization;
    attrs[0].val.programmaticStreamSerializationAllowed = 1;
    cfg.attrs = attrs;
    cfg.numAttrs = 1;
    cudaLaunchKernelEx(&cfg, capacity_kernel, out, osz);
}